// round 10
// baseline (speedup 1.0000x reference)
#include <cuda_runtime.h>
#include <cuda_bf16.h>
#include <math.h>
#include <stdint.h>

// ---------------- compile-time config ----------------
#define ROWS 32          // B (queries)
#define DMAX 1024
#define MAXSEL 1024
#define EQCAP 256
#define NBIN 4096
#define HCH 64
#define CAND 8192

// mma GEMM tiling
#define TN 128           // keys per CTA
#define KC 64            // dims per chunk
#define ASW 520          // A smem row stride (bf16) -> conflict-free a-frag LDS
#define KSW 72           // key smem row stride (bf16) -> conflict-free b-frag LDS
#define A_BYTES (64 * ASW * 2)          // 66560
#define KMAT_BYTES (TN * KSW * 2)       // 18432
#define GEMM2_DYN (A_BYTES + 4 * KMAT_BYTES + 512)

typedef unsigned long long ull;

// ---------------- scratch (device globals; no runtime allocation) ----------------
__device__ float g_pooled[ROWS * DMAX];
__device__ float g_query[ROWS * DMAX];
__device__ __nv_bfloat16 g_ab[64 * DMAX];        // rows 0-31: qh, rows 32-63: ql
__device__ float g_scores[(size_t)ROWS * 500224];
__device__ float g_sel_score[ROWS * MAXSEL];
__device__ int   g_sel_idx[ROWS * MAXSEL];
__device__ unsigned g_hist[ROWS][NBIN];
__device__ unsigned g_thr[ROWS];
__device__ int      g_ccnt[ROWS];
__device__ float    g_cscore[ROWS * CAND];
__device__ int      g_cidx[ROWS * CAND];

// ---------------- helpers ----------------
__device__ __forceinline__ void cpa16(void* dst_smem, const void* src) {
    unsigned s = (unsigned)__cvta_generic_to_shared(dst_smem);
    asm volatile("cp.async.cg.shared.global [%0], [%1], 16;" :: "r"(s), "l"(src) : "memory");
}
__device__ __forceinline__ void cp_commit() { asm volatile("cp.async.commit_group;" ::: "memory"); }
__device__ __forceinline__ void cp_wait0()  { asm volatile("cp.async.wait_group 0;" ::: "memory"); }

__device__ __forceinline__ unsigned flipf(float f) {
    unsigned u = __float_as_uint(f);
    return (u & 0x80000000u) ? ~u : (u | 0x80000000u);
}
__device__ __forceinline__ float unflipf(unsigned u) {
    return __uint_as_float((u & 0x80000000u) ? (u ^ 0x80000000u) : ~u);
}
__device__ __forceinline__ int eff_k(const int* kptr, const int* mkptr) {
    int k = kptr[0];
    int mk = mkptr[0];
    if (mk < k) k = mk;
    if (k < 1) k = 1;
    if (k > MAXSEL) k = MAXSEL;
    return k;
}
// pack two fp32 -> bf16x2, f0 in low half (element order)
__device__ __forceinline__ uint32_t pk_bf(float f0, float f1) {
    uint32_t r;
    asm("cvt.rn.bf16x2.f32 %0, %1, %2;" : "=r"(r) : "f"(f1), "f"(f0));
    return r;
}
__device__ __forceinline__ float bf_lo(uint32_t w) { return __uint_as_float(w << 16); }
__device__ __forceinline__ float bf_hi(uint32_t w) { return __uint_as_float(w & 0xFFFF0000u); }

// bf16 m16n8k16 tensor-core MMA (sm_80+ PTX; valid on compute_103 base target)
__device__ __forceinline__ void mma16816(float* c, const uint32_t* a, const uint32_t* b) {
    asm volatile("mma.sync.aligned.m16n8k16.row.col.f32.bf16.bf16.f32 "
                 "{%0,%1,%2,%3}, {%4,%5,%6,%7}, {%8,%9}, {%0,%1,%2,%3};"
                 : "+f"(c[0]), "+f"(c[1]), "+f"(c[2]), "+f"(c[3])
                 : "r"(a[0]), "r"(a[1]), "r"(a[2]), "r"(a[3]), "r"(b[0]), "r"(b[1]));
}

// ---------------- K1a: pooled = mean(hidden, axis=T) ----------------
__global__ __launch_bounds__(256) void pool_mean_kernel(
    const float* __restrict__ hidden, int B, int T, int D)
{
    int gt = blockIdx.x * blockDim.x + threadIdx.x;
    if (gt >= B * D) return;
    int b = gt / D;
    int d = gt - b * D;
    const float* p = hidden + (size_t)b * T * D + d;
    float s = 0.f;
    #pragma unroll 8
    for (int t = 0; t < T; t++) s += p[(size_t)t * D];
    g_pooled[gt] = s * (1.0f / (float)T);
}

// ---------------- K1b: query = pooled @ W + bias ----------------
__global__ __launch_bounds__(256) void query_proj_kernel(
    const float* __restrict__ W, const float* __restrict__ bias, int D)
{
    int b = blockIdx.x;
    int tid = threadIdx.x;
    __shared__ float sp[DMAX];
    for (int i = tid; i < D; i += blockDim.x) sp[i] = g_pooled[b * D + i];
    __syncthreads();
    for (int d = tid; d < D; d += blockDim.x) {
        float a = bias[d];
        #pragma unroll 8
        for (int kx = 0; kx < D; kx++) a += sp[kx] * W[(size_t)kx * D + d];
        g_query[b * D + d] = a;
    }
}

// ---------------- K1c: split query -> bf16 hi/lo A [64][D] ----------------
__global__ __launch_bounds__(256) void qsplit_kernel(int D)
{
    int i = blockIdx.x * blockDim.x + threadIdx.x;
    if (i >= 32 * D) return;
    int row = i / D;
    int col = i - row * D;
    float f = g_query[row * D + col];
    __nv_bfloat16 h = __float2bfloat16(f);
    g_ab[row * D + col] = h;
    g_ab[(row + 32) * D + col] = __float2bfloat16(f - __bfloat162float(h));
}

// ---------------- K2: split-bf16 tensor-core score GEMM ----------------
// CTA: TN=128 keys x D. A=[qh;ql] (M=64) resident in smem; keys streamed
// fp32 -> bf16 hi/lo per KC=64 chunk (double-buffered). Each warp owns
// (mt = wid>>2) score rows mt*16..+15 and (nq = wid&3) ntiles nq*4..+3,
// chaining 3 MMAs (qh*kh, ql*kh, qh*kl) into one fp32 accumulator.
extern __shared__ char gdyn[];
__global__ __launch_bounds__(256, 1) void gemm_mma_kernel(
    const float* __restrict__ keys, int N, int D, float scale)
{
    const int tid = threadIdx.x;
    const int lane = tid & 31;
    const int wid = tid >> 5;
    const int g = lane >> 2;        // 0..7
    const int tig = lane & 3;       // 0..3
    const int mt = wid >> 2;        // 0..1  (score rows mt*16..+15)
    const int nq = wid & 3;         // 0..3  (ntiles nq*4..+3)
    const long long nbase = (long long)blockIdx.x * TN;

    // 128B-align dynamic smem
    uint32_t raw;
    asm("{ .reg .u64 t; cvta.to.shared.u64 t, %1; cvt.u32.u64 %0, t; }" : "=r"(raw) : "l"(gdyn));
    char* base = gdyn + (((raw + 127u) & ~127u) - raw);

    __nv_bfloat16* A = (__nv_bfloat16*)base;                 // [64][ASW]
    char* kmat = base + A_BYTES;
    __nv_bfloat16* KH[2] = { (__nv_bfloat16*)kmat,
                             (__nv_bfloat16*)(kmat + 2 * KMAT_BYTES) };
    __nv_bfloat16* KL[2] = { (__nv_bfloat16*)(kmat + KMAT_BYTES),
                             (__nv_bfloat16*)(kmat + 3 * KMAT_BYTES) };

    // ---- load A (qh/ql) into smem with padded stride, cp.async ----
    {
        const int perrow = D / 8;                 // 16B chunks per row
        const int total = 64 * perrow;
        for (int slot = tid; slot < total; slot += 256) {
            int row = slot / perrow;
            int c16 = slot - row * perrow;
            cpa16((char*)(A + row * ASW) + c16 * 16, g_ab + (size_t)row * D + c16 * 8);
        }
        cp_commit();
    }

    const int nch = D / KC;
    float acc[4][4];
    #pragma unroll
    for (int t = 0; t < 4; t++)
        #pragma unroll
        for (int j = 0; j < 4; j++) acc[t][j] = 0.f;

    // key row/half owned by this thread for staging
    const int krow = tid >> 1;          // 0..127
    const int khalf = tid & 1;          // 0..1 (32 floats each)
    long long grow = nbase + krow;
    if (grow >= N) grow = N - 1;
    const float* kbase = keys + grow * (long long)D + khalf * 32;

    float4 R[8];
    #pragma unroll
    for (int q4 = 0; q4 < 8; q4++) R[q4] = *(const float4*)(kbase + 0 * KC + q4 * 4);

    cp_wait0();   // A resident

    for (int c = 0; c < nch; c++) {
        const int st = c & 1;
        // STS current chunk (convert fp32 -> bf16 hi/lo)
        {
            uint32_t hw[16], lw[16];
            const float* f = (const float*)R;
            #pragma unroll
            for (int p = 0; p < 16; p++) {
                float f0 = f[2 * p], f1 = f[2 * p + 1];
                hw[p] = pk_bf(f0, f1);
                lw[p] = pk_bf(f0 - bf_lo(hw[p]), f1 - bf_hi(hw[p]));
            }
            uint4* dh = (uint4*)((char*)(KH[st] + krow * KSW + khalf * 32));
            uint4* dl = (uint4*)((char*)(KL[st] + krow * KSW + khalf * 32));
            #pragma unroll
            for (int v = 0; v < 4; v++) {
                dh[v] = make_uint4(hw[4 * v], hw[4 * v + 1], hw[4 * v + 2], hw[4 * v + 3]);
                dl[v] = make_uint4(lw[4 * v], lw[4 * v + 1], lw[4 * v + 2], lw[4 * v + 3]);
            }
        }
        // prefetch next chunk into registers (overlaps with compute below)
        if (c + 1 < nch) {
            #pragma unroll
            for (int q4 = 0; q4 < 8; q4++)
                R[q4] = *(const float4*)(kbase + (c + 1) * KC + q4 * 4);
        }
        __syncthreads();

        // ---- compute chunk c ----
        #pragma unroll
        for (int ks = 0; ks < KC / 16; ks++) {
            const int k0 = ks * 16;
            uint32_t aqh[4], aql[4];
            {
                // FIX (R9 bug): A columns for chunk c start at c*KC.
                const __nv_bfloat16* Ah = A + (mt * 16 + g) * ASW + c * KC + k0 + 2 * tig;
                const __nv_bfloat16* Al = A + (32 + mt * 16 + g) * ASW + c * KC + k0 + 2 * tig;
                aqh[0] = *(const uint32_t*)Ah;
                aqh[1] = *(const uint32_t*)(Ah + 8 * ASW);
                aqh[2] = *(const uint32_t*)(Ah + 8);
                aqh[3] = *(const uint32_t*)(Ah + 8 * ASW + 8);
                aql[0] = *(const uint32_t*)Al;
                aql[1] = *(const uint32_t*)(Al + 8 * ASW);
                aql[2] = *(const uint32_t*)(Al + 8);
                aql[3] = *(const uint32_t*)(Al + 8 * ASW + 8);
            }
            #pragma unroll
            for (int t = 0; t < 4; t++) {
                const int nt = nq * 4 + t;
                const __nv_bfloat16* bh = KH[st] + (nt * 8 + g) * KSW + k0 + 2 * tig;
                const __nv_bfloat16* bl = KL[st] + (nt * 8 + g) * KSW + k0 + 2 * tig;
                uint32_t bkh[2], bkl[2];
                bkh[0] = *(const uint32_t*)bh;
                bkh[1] = *(const uint32_t*)(bh + 8);
                bkl[0] = *(const uint32_t*)bl;
                bkl[1] = *(const uint32_t*)(bl + 8);
                mma16816(acc[t], aqh, bkh);
                mma16816(acc[t], aql, bkh);
                mma16816(acc[t], aqh, bkl);
            }
        }
        __syncthreads();   // stage free for reuse
    }

    // ---- epilogue: write scores ----
    #pragma unroll
    for (int t = 0; t < 4; t++) {
        const int nt = nq * 4 + t;
        long long col = nbase + nt * 8 + 2 * tig;
        int row0 = mt * 16 + g;
        if (col + 1 < N) {
            *(float2*)&g_scores[(size_t)row0 * N + col] =
                make_float2(acc[t][0] * scale, acc[t][1] * scale);
            *(float2*)&g_scores[(size_t)(row0 + 8) * N + col] =
                make_float2(acc[t][2] * scale, acc[t][3] * scale);
        } else if (col < N) {
            g_scores[(size_t)row0 * N + col] = acc[t][0] * scale;
            g_scores[(size_t)(row0 + 8) * N + col] = acc[t][2] * scale;
        }
    }
}

// ---------------- K3a: zero scratch ----------------
__global__ __launch_bounds__(256) void zero_scratch_kernel()
{
    int i = blockIdx.x * blockDim.x + threadIdx.x;
    if (i < ROWS * NBIN) ((unsigned*)g_hist)[i] = 0;
    if (i < ROWS) g_ccnt[i] = 0;
}

// ---------------- K3b: grid-parallel per-row histogram ----------------
__global__ __launch_bounds__(256) void hist_kernel(int N)
{
    const int r = blockIdx.y;
    const int c = blockIdx.x;
    const int tid = threadIdx.x;
    __shared__ unsigned sh[NBIN];
    for (int i = tid; i < NBIN; i += 256) sh[i] = 0;
    __syncthreads();

    const int per = (N + HCH - 1) / HCH;
    const int s = c * per;
    const int e = (s + per < N) ? s + per : N;
    const float* srow = g_scores + (size_t)r * N;
    for (int i = s + tid; i < e; i += 256)
        atomicAdd(&sh[flipf(srow[i]) >> 20], 1u);
    __syncthreads();

    for (int i = tid; i < NBIN; i += 256)
        if (sh[i]) atomicAdd(&g_hist[r][i], sh[i]);
}

// ---------------- K3c: per-row threshold bin ----------------
__global__ __launch_bounds__(256) void threshold_kernel(
    const int* __restrict__ kptr, const int* __restrict__ mkptr)
{
    const int r = blockIdx.x;
    const int tid = threadIdx.x;
    __shared__ unsigned h[NBIN];
    __shared__ unsigned sfx[257];
    __shared__ int selg;

    const int k = eff_k(kptr, mkptr);
    for (int i = tid; i < NBIN; i += 256) h[i] = g_hist[r][i];
    __syncthreads();

    unsigned gsum = 0;
    #pragma unroll
    for (int b = 0; b < 16; b++) gsum += h[tid * 16 + b];
    sfx[tid] = gsum;
    if (tid == 0) sfx[256] = 0;
    __syncthreads();
    for (int off = 1; off < 256; off <<= 1) {
        unsigned t = (tid + off < 256) ? sfx[tid + off] : 0u;
        __syncthreads();
        sfx[tid] += t;
        __syncthreads();
    }
    unsigned above = (tid < 255) ? sfx[tid + 1] : 0u;
    if ((int)above < k && (int)sfx[tid] >= k) selg = tid;
    __syncthreads();

    if (tid == 0) {
        int g = selg;
        unsigned cum = (g < 255) ? sfx[g + 1] : 0u;
        int bsel = g * 16;
        for (int b = g * 16 + 15; b >= g * 16; b--) {
            cum += h[b];
            if ((int)cum >= k) { bsel = b; break; }
        }
        g_thr[r] = ((unsigned)bsel) << 20;
    }
}

// ---------------- K3d: compaction ----------------
__global__ __launch_bounds__(256) void compact_kernel(int N)
{
    const int r = blockIdx.y;
    const int c = blockIdx.x;
    const int tid = threadIdx.x;
    const unsigned thr = g_thr[r];

    const int per = (N + HCH - 1) / HCH;
    const int s = c * per;
    const int e = (s + per < N) ? s + per : N;
    const float* srow = g_scores + (size_t)r * N;
    for (int i = s + tid; i < e; i += 256) {
        float v = srow[i];
        if (flipf(v) >= thr) {
            int p = atomicAdd(&g_ccnt[r], 1);
            if (p < CAND) {
                g_cscore[r * CAND + p] = v;
                g_cidx[r * CAND + p] = i;
            }
        }
    }
}

// ---------------- K3e: exact top-k over candidates ----------------
#define SEL_T 256
__global__ __launch_bounds__(SEL_T) void topk_final_kernel(
    const int* __restrict__ kptr, const int* __restrict__ mkptr)
{
    const int r = blockIdx.x;
    const int tid = threadIdx.x;
    int M = g_ccnt[r];
    if (M > CAND) M = CAND;
    int k = eff_k(kptr, mkptr);
    if (k > M) k = M;

    const float* cs = g_cscore + r * CAND;
    const int*   ci = g_cidx + r * CAND;

    __shared__ unsigned bins[256];
    __shared__ unsigned sfx[257];
    __shared__ unsigned sh_prefix;
    __shared__ int sh_need;
    __shared__ int sh_selv;

    if (tid == 0) { sh_prefix = 0; sh_need = k; }
    __syncthreads();

    for (int pass = 0; pass < 4; pass++) {
        const int shift = 24 - 8 * pass;
        const unsigned hmask = pass ? (0xFFFFFFFFu << (shift + 8)) : 0u;
        bins[tid] = 0;
        __syncthreads();
        const unsigned pref = sh_prefix;
        for (int i = tid; i < M; i += SEL_T) {
            unsigned u = flipf(cs[i]);
            if ((u & hmask) == pref)
                atomicAdd(&bins[(u >> shift) & 255u], 1u);
        }
        __syncthreads();
        sfx[tid] = bins[tid];
        if (tid == 0) sfx[256] = 0;
        __syncthreads();
        for (int off = 1; off < 256; off <<= 1) {
            unsigned t = (tid + off < 256) ? sfx[tid + off] : 0u;
            __syncthreads();
            sfx[tid] += t;
            __syncthreads();
        }
        const int need = sh_need;
        const unsigned above = (tid < 255) ? sfx[tid + 1] : 0u;
        if ((int)above < need && (int)sfx[tid] >= need)
            sh_selv = tid;
        __syncthreads();
        if (tid == 0) {
            int v = sh_selv;
            sh_need = need - (int)((v < 255) ? sfx[v + 1] : 0u);
            sh_prefix = pref | ((unsigned)v << shift);
        }
        __syncthreads();
    }

    const unsigned uk = sh_prefix;
    const int need = sh_need;

    __shared__ int cg, ce;
    __shared__ int eq[EQCAP];
    if (tid == 0) { cg = 0; ce = 0; }
    __syncthreads();

    for (int i = tid; i < M; i += SEL_T) {
        unsigned u = flipf(cs[i]);
        if (u > uk) {
            int p = atomicAdd(&cg, 1);
            g_sel_score[r * MAXSEL + p] = cs[i];
            g_sel_idx[r * MAXSEL + p] = ci[i];
        } else if (u == uk) {
            int p = atomicAdd(&ce, 1);
            if (p < EQCAP) eq[p] = ci[i];
        }
    }
    __syncthreads();

    if (tid == 0) {
        const float tie_score = unflipf(uk);
        int base = cg;
        int ne = ce < EQCAP ? ce : EQCAP;
        for (int t = 0; t < need; t++) {
            int mv = 0x7FFFFFFF, mi = -1;
            for (int j = 0; j < ne; j++)
                if (eq[j] < mv) { mv = eq[j]; mi = j; }
            if (mi >= 0) eq[mi] = 0x7FFFFFFF;
            g_sel_idx[r * MAXSEL + base + t] = mv;
            g_sel_score[r * MAXSEL + base + t] = tie_score;
        }
        for (int a = 0; a < k - 1; a++) {
            int best = a;
            for (int bidx = a + 1; bidx < k; bidx++)
                if (g_sel_idx[r * MAXSEL + bidx] < g_sel_idx[r * MAXSEL + best]) best = bidx;
            if (best != a) {
                int ti = g_sel_idx[r * MAXSEL + a];
                g_sel_idx[r * MAXSEL + a] = g_sel_idx[r * MAXSEL + best];
                g_sel_idx[r * MAXSEL + best] = ti;
                float ts = g_sel_score[r * MAXSEL + a];
                g_sel_score[r * MAXSEL + a] = g_sel_score[r * MAXSEL + best];
                g_sel_score[r * MAXSEL + best] = ts;
            }
        }
    }
}

// ---------------- K4: softmax + weighted gather ----------------
__global__ __launch_bounds__(256) void aggregate_kernel(
    const float* __restrict__ params, float* __restrict__ out,
    int D, const int* __restrict__ kptr, const int* __restrict__ mkptr)
{
    const int r = blockIdx.x;
    const int tid = threadIdx.x;
    const int k = eff_k(kptr, mkptr);

    __shared__ float w[MAXSEL];
    __shared__ int sidx[MAXSEL];

    for (int i = tid; i < k; i += blockDim.x) {
        w[i] = g_sel_score[r * MAXSEL + i];
        sidx[i] = g_sel_idx[r * MAXSEL + i];
    }
    __syncthreads();
    if (tid == 0) {
        float m = -3.402823e38f;
        for (int i = 0; i < k; i++) m = fmaxf(m, w[i]);
        float s = 0.f;
        for (int i = 0; i < k; i++) { w[i] = expf(w[i] - m); s += w[i]; }
        float inv = 1.0f / s;
        for (int i = 0; i < k; i++) w[i] *= inv;
    }
    __syncthreads();

    for (int d = tid; d < D; d += blockDim.x) {
        float a = 0.f;
        for (int i = 0; i < k; i++)
            a += w[i] * params[(size_t)sidx[i] * D + d];
        out[(size_t)r * D + d] = a;
    }
}

// ---------------- launch ----------------
extern "C" void kernel_launch(void* const* d_in, const int* in_sizes, int n_in,
                              void* d_out, int out_size)
{
    const float* hidden = (const float*)d_in[0];
    const float* params = (const float*)d_in[1];
    const float* keys   = (const float*)d_in[2];
    const float* W      = (const float*)d_in[3];
    const float* bias   = (const float*)d_in[4];
    const int*   kptr   = (const int*)d_in[5];
    const int*   mkptr  = (const int*)d_in[6];

    int D = (int)(sqrt((double)in_sizes[3]) + 0.5);   // W [D, D]
    int B = out_size / D;                              // out [B, D]
    int N = in_sizes[2] / D;                           // keys [N, D]
    int T = in_sizes[0] / (B * D);                     // hidden [B, T, D]
    float scale = 1.0f / sqrtf((float)D);

    float* out = (float*)d_out;

    cudaFuncSetAttribute(gemm_mma_kernel,
                         cudaFuncAttributeMaxDynamicSharedMemorySize, GEMM2_DYN);

    pool_mean_kernel<<<(B * D + 255) / 256, 256>>>(hidden, B, T, D);
    query_proj_kernel<<<B, 256>>>(W, bias, D);
    qsplit_kernel<<<(32 * D + 255) / 256, 256>>>(D);
    gemm_mma_kernel<<<(N + TN - 1) / TN, 256, GEMM2_DYN>>>(keys, N, D, scale);
    zero_scratch_kernel<<<(ROWS * NBIN + 255) / 256, 256>>>();
    hist_kernel<<<dim3(HCH, B), 256>>>(N);
    threshold_kernel<<<B, 256>>>(kptr, mkptr);
    compact_kernel<<<dim3(HCH, B), 256>>>(N);
    topk_final_kernel<<<B, SEL_T>>>(kptr, mkptr);
    aggregate_kernel<<<B, 256>>>(params, out, D, kptr, mkptr);
}

// round 11
// speedup vs baseline: 1.1014x; 1.1014x over previous
#include <cuda_runtime.h>
#include <cuda_bf16.h>
#include <math.h>
#include <stdint.h>

// ---------------- compile-time config ----------------
#define ROWS 32          // B (queries)
#define DMAX 1024
#define MAXSEL 1024
#define EQCAP 256
#define NBIN 4096
#define HCH 64
#define CAND 8192

// mma GEMM tiling
#define TN 128           // keys per CTA
#define KC 64            // dims per chunk
#define ASW2 72          // A chunk smem row stride (bf16) -> conflict-free a-frag LDS
#define KSW 72           // key smem row stride (bf16) -> conflict-free b-frag LDS
#define A_CH_BYTES (64 * ASW2 * 2)      // 9216
#define KMAT_BYTES (TN * KSW * 2)       // 18432
#define STAGE_B (A_CH_BYTES + 2 * KMAT_BYTES)   // 46080
#define GEMM2_DYN (2 * STAGE_B + 256)

typedef unsigned long long ull;

// ---------------- scratch (device globals; no runtime allocation) ----------------
__device__ float g_pooled[ROWS * DMAX];
__device__ float g_query[ROWS * DMAX];
__device__ __nv_bfloat16 g_ab[64 * DMAX];        // rows 0-31: qh, rows 32-63: ql
__device__ float g_scores[(size_t)ROWS * 500224];
__device__ float g_sel_score[ROWS * MAXSEL];
__device__ int   g_sel_idx[ROWS * MAXSEL];
__device__ unsigned g_hist[ROWS][NBIN];
__device__ unsigned g_thr[ROWS];
__device__ int      g_ccnt[ROWS];
__device__ float    g_cscore[ROWS * CAND];
__device__ int      g_cidx[ROWS * CAND];

// ---------------- helpers ----------------
__device__ __forceinline__ void cpa16(void* dst_smem, const void* src) {
    unsigned s = (unsigned)__cvta_generic_to_shared(dst_smem);
    asm volatile("cp.async.cg.shared.global [%0], [%1], 16;" :: "r"(s), "l"(src) : "memory");
}
__device__ __forceinline__ void cp_commit() { asm volatile("cp.async.commit_group;" ::: "memory"); }
__device__ __forceinline__ void cp_wait1()  { asm volatile("cp.async.wait_group 1;" ::: "memory"); }
__device__ __forceinline__ void cp_wait0()  { asm volatile("cp.async.wait_group 0;" ::: "memory"); }

__device__ __forceinline__ unsigned flipf(float f) {
    unsigned u = __float_as_uint(f);
    return (u & 0x80000000u) ? ~u : (u | 0x80000000u);
}
__device__ __forceinline__ float unflipf(unsigned u) {
    return __uint_as_float((u & 0x80000000u) ? (u ^ 0x80000000u) : ~u);
}
__device__ __forceinline__ int eff_k(const int* kptr, const int* mkptr) {
    int k = kptr[0];
    int mk = mkptr[0];
    if (mk < k) k = mk;
    if (k < 1) k = 1;
    if (k > MAXSEL) k = MAXSEL;
    return k;
}
// pack two fp32 -> bf16x2, f0 in low half (element order)
__device__ __forceinline__ uint32_t pk_bf(float f0, float f1) {
    uint32_t r;
    asm("cvt.rn.bf16x2.f32 %0, %1, %2;" : "=r"(r) : "f"(f1), "f"(f0));
    return r;
}
__device__ __forceinline__ float bf_lo(uint32_t w) { return __uint_as_float(w << 16); }
__device__ __forceinline__ float bf_hi(uint32_t w) { return __uint_as_float(w & 0xFFFF0000u); }

// bf16 m16n8k16 tensor-core MMA (sm_80+ PTX; valid on compute_103 base target)
__device__ __forceinline__ void mma16816(float* c, const uint32_t* a, const uint32_t* b) {
    asm volatile("mma.sync.aligned.m16n8k16.row.col.f32.bf16.bf16.f32 "
                 "{%0,%1,%2,%3}, {%4,%5,%6,%7}, {%8,%9}, {%0,%1,%2,%3};"
                 : "+f"(c[0]), "+f"(c[1]), "+f"(c[2]), "+f"(c[3])
                 : "r"(a[0]), "r"(a[1]), "r"(a[2]), "r"(a[3]), "r"(b[0]), "r"(b[1]));
}

// ---------------- K1a: pooled = mean(hidden, axis=T) ----------------
__global__ __launch_bounds__(256) void pool_mean_kernel(
    const float* __restrict__ hidden, int B, int T, int D)
{
    int gt = blockIdx.x * blockDim.x + threadIdx.x;
    if (gt >= B * D) return;
    int b = gt / D;
    int d = gt - b * D;
    const float* p = hidden + (size_t)b * T * D + d;
    float s = 0.f;
    #pragma unroll 8
    for (int t = 0; t < T; t++) s += p[(size_t)t * D];
    g_pooled[gt] = s * (1.0f / (float)T);
}

// ---------------- K1b: query = pooled @ W + bias ----------------
__global__ __launch_bounds__(256) void query_proj_kernel(
    const float* __restrict__ W, const float* __restrict__ bias, int D)
{
    int b = blockIdx.x;
    int tid = threadIdx.x;
    __shared__ float sp[DMAX];
    for (int i = tid; i < D; i += blockDim.x) sp[i] = g_pooled[b * D + i];
    __syncthreads();
    for (int d = tid; d < D; d += blockDim.x) {
        float a = bias[d];
        #pragma unroll 8
        for (int kx = 0; kx < D; kx++) a += sp[kx] * W[(size_t)kx * D + d];
        g_query[b * D + d] = a;
    }
}

// ---------------- K1c: split query -> bf16 hi/lo A [64][D] ----------------
__global__ __launch_bounds__(256) void qsplit_kernel(int D)
{
    int i = blockIdx.x * blockDim.x + threadIdx.x;
    if (i >= 32 * D) return;
    int row = i / D;
    int col = i - row * D;
    float f = g_query[row * D + col];
    __nv_bfloat16 h = __float2bfloat16(f);
    g_ab[row * D + col] = h;
    g_ab[(row + 32) * D + col] = __float2bfloat16(f - __bfloat162float(h));
}

// ---------------- K2: split-bf16 tensor-core score GEMM ----------------
// CTA: TN=128 keys x D. Both A ([qh;ql], 64xKC per chunk, cp.async) and keys
// (fp32 -> bf16 hi/lo in-register, STS) are streamed per KC=64 chunk,
// double-buffered. Stage = 46KB -> 92KB/CTA -> 2 CTAs/SM (occupancy fix vs R10:
// occ was 12.6% with resident A at 140KB/CTA). Each warp: score rows mt*16..+15,
// ntiles nq*4..+3, 3 chained MMAs (qh*kh, ql*kh, qh*kl) per fragment.
extern __shared__ char gdyn[];
__global__ __launch_bounds__(256, 2) void gemm_mma_kernel(
    const float* __restrict__ keys, int N, int D, float scale)
{
    const int tid = threadIdx.x;
    const int lane = tid & 31;
    const int wid = tid >> 5;
    const int g = lane >> 2;        // 0..7
    const int tig = lane & 3;       // 0..3
    const int mt = wid >> 2;        // 0..1  (score rows mt*16..+15)
    const int nq = wid & 3;         // 0..3  (ntiles nq*4..+3)
    const long long nbase = (long long)blockIdx.x * TN;

    // 128B-align dynamic smem
    uint32_t raw;
    asm("{ .reg .u64 t; cvta.to.shared.u64 t, %1; cvt.u32.u64 %0, t; }" : "=r"(raw) : "l"(gdyn));
    char* base = gdyn + (((raw + 127u) & ~127u) - raw);

    // per-stage layout: [A 64xASW2][KH TNxKSW][KL TNxKSW]
    __nv_bfloat16* Ast[2] = { (__nv_bfloat16*)base,
                              (__nv_bfloat16*)(base + STAGE_B) };
    __nv_bfloat16* KH[2]  = { (__nv_bfloat16*)(base + A_CH_BYTES),
                              (__nv_bfloat16*)(base + STAGE_B + A_CH_BYTES) };
    __nv_bfloat16* KL[2]  = { (__nv_bfloat16*)(base + A_CH_BYTES + KMAT_BYTES),
                              (__nv_bfloat16*)(base + STAGE_B + A_CH_BYTES + KMAT_BYTES) };

    const int nch = D / KC;

    // A chunk loader: 64 rows x KC cols (KC*2=128B per row = 8 x 16B), 512 slots, 2/thread
    auto load_A = [&](int st, int c) {
        #pragma unroll
        for (int it = 0; it < 2; it++) {
            int slot = tid + it * 256;        // 0..511
            int row = slot >> 3;              // 0..63
            int c16 = slot & 7;               // 16B chunk in row
            cpa16((char*)(Ast[st] + row * ASW2) + c16 * 16,
                  g_ab + (size_t)row * D + c * KC + c16 * 8);
        }
        cp_commit();
    };

    float acc[4][4];
    #pragma unroll
    for (int t = 0; t < 4; t++)
        #pragma unroll
        for (int j = 0; j < 4; j++) acc[t][j] = 0.f;

    // key row/half owned by this thread for staging
    const int krow = tid >> 1;          // 0..127
    const int khalf = tid & 1;          // 0..1 (32 floats each)
    long long grow = nbase + krow;
    if (grow >= N) grow = N - 1;
    const float* kbase = keys + grow * (long long)D + khalf * 32;

    // preload chunk 0
    load_A(0, 0);
    float4 R[8];
    #pragma unroll
    for (int q4 = 0; q4 < 8; q4++) R[q4] = *(const float4*)(kbase + q4 * 4);

    for (int c = 0; c < nch; c++) {
        const int st = c & 1;
        // STS keys chunk c (convert fp32 -> bf16 hi/lo), 16B at a time
        {
            uint4* dh = (uint4*)((char*)(KH[st] + krow * KSW + khalf * 32));
            uint4* dl = (uint4*)((char*)(KL[st] + krow * KSW + khalf * 32));
            #pragma unroll
            for (int v = 0; v < 4; v++) {
                const float* f = (const float*)&R[2 * v];   // 8 floats
                uint32_t hw[4], lw[4];
                #pragma unroll
                for (int p = 0; p < 4; p++) {
                    float f0 = f[2 * p], f1 = f[2 * p + 1];
                    hw[p] = pk_bf(f0, f1);
                    lw[p] = pk_bf(f0 - bf_lo(hw[p]), f1 - bf_hi(hw[p]));
                }
                dh[v] = make_uint4(hw[0], hw[1], hw[2], hw[3]);
                dl[v] = make_uint4(lw[0], lw[1], lw[2], lw[3]);
            }
        }
        // prefetch chunk c+1 (A via cp.async into other stage; keys via LDG)
        if (c + 1 < nch) {
            load_A(st ^ 1, c + 1);
            #pragma unroll
            for (int q4 = 0; q4 < 8; q4++)
                R[q4] = *(const float4*)(kbase + (c + 1) * KC + q4 * 4);
            cp_wait1();    // A(c) complete; A(c+1) may remain in flight
        } else {
            cp_wait0();
        }
        __syncthreads();

        // ---- compute chunk c ----
        const __nv_bfloat16* A = Ast[st];
        #pragma unroll
        for (int ks = 0; ks < KC / 16; ks++) {
            const int k0 = ks * 16;
            uint32_t aqh[4], aql[4];
            {
                const __nv_bfloat16* Ah = A + (mt * 16 + g) * ASW2 + k0 + 2 * tig;
                const __nv_bfloat16* Al = A + (32 + mt * 16 + g) * ASW2 + k0 + 2 * tig;
                aqh[0] = *(const uint32_t*)Ah;
                aqh[1] = *(const uint32_t*)(Ah + 8 * ASW2);
                aqh[2] = *(const uint32_t*)(Ah + 8);
                aqh[3] = *(const uint32_t*)(Ah + 8 * ASW2 + 8);
                aql[0] = *(const uint32_t*)Al;
                aql[1] = *(const uint32_t*)(Al + 8 * ASW2);
                aql[2] = *(const uint32_t*)(Al + 8);
                aql[3] = *(const uint32_t*)(Al + 8 * ASW2 + 8);
            }
            #pragma unroll
            for (int t = 0; t < 4; t++) {
                const int nt = nq * 4 + t;
                const __nv_bfloat16* bh = KH[st] + (nt * 8 + g) * KSW + k0 + 2 * tig;
                const __nv_bfloat16* bl = KL[st] + (nt * 8 + g) * KSW + k0 + 2 * tig;
                uint32_t bkh[2], bkl[2];
                bkh[0] = *(const uint32_t*)bh;
                bkh[1] = *(const uint32_t*)(bh + 8);
                bkl[0] = *(const uint32_t*)bl;
                bkl[1] = *(const uint32_t*)(bl + 8);
                mma16816(acc[t], aqh, bkh);
                mma16816(acc[t], aql, bkh);
                mma16816(acc[t], aqh, bkl);
            }
        }
        __syncthreads();   // stage free for reuse
    }

    // ---- epilogue: write scores ----
    #pragma unroll
    for (int t = 0; t < 4; t++) {
        const int nt = nq * 4 + t;
        long long col = nbase + nt * 8 + 2 * tig;
        int row0 = mt * 16 + g;
        if (col + 1 < N) {
            *(float2*)&g_scores[(size_t)row0 * N + col] =
                make_float2(acc[t][0] * scale, acc[t][1] * scale);
            *(float2*)&g_scores[(size_t)(row0 + 8) * N + col] =
                make_float2(acc[t][2] * scale, acc[t][3] * scale);
        } else if (col < N) {
            g_scores[(size_t)row0 * N + col] = acc[t][0] * scale;
            g_scores[(size_t)(row0 + 8) * N + col] = acc[t][2] * scale;
        }
    }
}

// ---------------- K3a: zero scratch ----------------
__global__ __launch_bounds__(256) void zero_scratch_kernel()
{
    int i = blockIdx.x * blockDim.x + threadIdx.x;
    if (i < ROWS * NBIN) ((unsigned*)g_hist)[i] = 0;
    if (i < ROWS) g_ccnt[i] = 0;
}

// ---------------- K3b: grid-parallel per-row histogram ----------------
__global__ __launch_bounds__(256) void hist_kernel(int N)
{
    const int r = blockIdx.y;
    const int c = blockIdx.x;
    const int tid = threadIdx.x;
    __shared__ unsigned sh[NBIN];
    for (int i = tid; i < NBIN; i += 256) sh[i] = 0;
    __syncthreads();

    const int per = (N + HCH - 1) / HCH;
    const int s = c * per;
    const int e = (s + per < N) ? s + per : N;
    const float* srow = g_scores + (size_t)r * N;
    for (int i = s + tid; i < e; i += 256)
        atomicAdd(&sh[flipf(srow[i]) >> 20], 1u);
    __syncthreads();

    for (int i = tid; i < NBIN; i += 256)
        if (sh[i]) atomicAdd(&g_hist[r][i], sh[i]);
}

// ---------------- K3c: per-row threshold bin ----------------
__global__ __launch_bounds__(256) void threshold_kernel(
    const int* __restrict__ kptr, const int* __restrict__ mkptr)
{
    const int r = blockIdx.x;
    const int tid = threadIdx.x;
    __shared__ unsigned h[NBIN];
    __shared__ unsigned sfx[257];
    __shared__ int selg;

    const int k = eff_k(kptr, mkptr);
    for (int i = tid; i < NBIN; i += 256) h[i] = g_hist[r][i];
    __syncthreads();

    unsigned gsum = 0;
    #pragma unroll
    for (int b = 0; b < 16; b++) gsum += h[tid * 16 + b];
    sfx[tid] = gsum;
    if (tid == 0) sfx[256] = 0;
    __syncthreads();
    for (int off = 1; off < 256; off <<= 1) {
        unsigned t = (tid + off < 256) ? sfx[tid + off] : 0u;
        __syncthreads();
        sfx[tid] += t;
        __syncthreads();
    }
    unsigned above = (tid < 255) ? sfx[tid + 1] : 0u;
    if ((int)above < k && (int)sfx[tid] >= k) selg = tid;
    __syncthreads();

    if (tid == 0) {
        int g = selg;
        unsigned cum = (g < 255) ? sfx[g + 1] : 0u;
        int bsel = g * 16;
        for (int b = g * 16 + 15; b >= g * 16; b--) {
            cum += h[b];
            if ((int)cum >= k) { bsel = b; break; }
        }
        g_thr[r] = ((unsigned)bsel) << 20;
    }
}

// ---------------- K3d: compaction ----------------
__global__ __launch_bounds__(256) void compact_kernel(int N)
{
    const int r = blockIdx.y;
    const int c = blockIdx.x;
    const int tid = threadIdx.x;
    const unsigned thr = g_thr[r];

    const int per = (N + HCH - 1) / HCH;
    const int s = c * per;
    const int e = (s + per < N) ? s + per : N;
    const float* srow = g_scores + (size_t)r * N;
    for (int i = s + tid; i < e; i += 256) {
        float v = srow[i];
        if (flipf(v) >= thr) {
            int p = atomicAdd(&g_ccnt[r], 1);
            if (p < CAND) {
                g_cscore[r * CAND + p] = v;
                g_cidx[r * CAND + p] = i;
            }
        }
    }
}

// ---------------- K3e: exact top-k over candidates ----------------
#define SEL_T 256
__global__ __launch_bounds__(SEL_T) void topk_final_kernel(
    const int* __restrict__ kptr, const int* __restrict__ mkptr)
{
    const int r = blockIdx.x;
    const int tid = threadIdx.x;
    int M = g_ccnt[r];
    if (M > CAND) M = CAND;
    int k = eff_k(kptr, mkptr);
    if (k > M) k = M;

    const float* cs = g_cscore + r * CAND;
    const int*   ci = g_cidx + r * CAND;

    __shared__ unsigned bins[256];
    __shared__ unsigned sfx[257];
    __shared__ unsigned sh_prefix;
    __shared__ int sh_need;
    __shared__ int sh_selv;

    if (tid == 0) { sh_prefix = 0; sh_need = k; }
    __syncthreads();

    for (int pass = 0; pass < 4; pass++) {
        const int shift = 24 - 8 * pass;
        const unsigned hmask = pass ? (0xFFFFFFFFu << (shift + 8)) : 0u;
        bins[tid] = 0;
        __syncthreads();
        const unsigned pref = sh_prefix;
        for (int i = tid; i < M; i += SEL_T) {
            unsigned u = flipf(cs[i]);
            if ((u & hmask) == pref)
                atomicAdd(&bins[(u >> shift) & 255u], 1u);
        }
        __syncthreads();
        sfx[tid] = bins[tid];
        if (tid == 0) sfx[256] = 0;
        __syncthreads();
        for (int off = 1; off < 256; off <<= 1) {
            unsigned t = (tid + off < 256) ? sfx[tid + off] : 0u;
            __syncthreads();
            sfx[tid] += t;
            __syncthreads();
        }
        const int need = sh_need;
        const unsigned above = (tid < 255) ? sfx[tid + 1] : 0u;
        if ((int)above < need && (int)sfx[tid] >= need)
            sh_selv = tid;
        __syncthreads();
        if (tid == 0) {
            int v = sh_selv;
            sh_need = need - (int)((v < 255) ? sfx[v + 1] : 0u);
            sh_prefix = pref | ((unsigned)v << shift);
        }
        __syncthreads();
    }

    const unsigned uk = sh_prefix;
    const int need = sh_need;

    __shared__ int cg, ce;
    __shared__ int eq[EQCAP];
    if (tid == 0) { cg = 0; ce = 0; }
    __syncthreads();

    for (int i = tid; i < M; i += SEL_T) {
        unsigned u = flipf(cs[i]);
        if (u > uk) {
            int p = atomicAdd(&cg, 1);
            g_sel_score[r * MAXSEL + p] = cs[i];
            g_sel_idx[r * MAXSEL + p] = ci[i];
        } else if (u == uk) {
            int p = atomicAdd(&ce, 1);
            if (p < EQCAP) eq[p] = ci[i];
        }
    }
    __syncthreads();

    if (tid == 0) {
        const float tie_score = unflipf(uk);
        int base = cg;
        int ne = ce < EQCAP ? ce : EQCAP;
        for (int t = 0; t < need; t++) {
            int mv = 0x7FFFFFFF, mi = -1;
            for (int j = 0; j < ne; j++)
                if (eq[j] < mv) { mv = eq[j]; mi = j; }
            if (mi >= 0) eq[mi] = 0x7FFFFFFF;
            g_sel_idx[r * MAXSEL + base + t] = mv;
            g_sel_score[r * MAXSEL + base + t] = tie_score;
        }
        for (int a = 0; a < k - 1; a++) {
            int best = a;
            for (int bidx = a + 1; bidx < k; bidx++)
                if (g_sel_idx[r * MAXSEL + bidx] < g_sel_idx[r * MAXSEL + best]) best = bidx;
            if (best != a) {
                int ti = g_sel_idx[r * MAXSEL + a];
                g_sel_idx[r * MAXSEL + a] = g_sel_idx[r * MAXSEL + best];
                g_sel_idx[r * MAXSEL + best] = ti;
                float ts = g_sel_score[r * MAXSEL + a];
                g_sel_score[r * MAXSEL + a] = g_sel_score[r * MAXSEL + best];
                g_sel_score[r * MAXSEL + best] = ts;
            }
        }
    }
}

// ---------------- K4: softmax + weighted gather ----------------
__global__ __launch_bounds__(256) void aggregate_kernel(
    const float* __restrict__ params, float* __restrict__ out,
    int D, const int* __restrict__ kptr, const int* __restrict__ mkptr)
{
    const int r = blockIdx.x;
    const int tid = threadIdx.x;
    const int k = eff_k(kptr, mkptr);

    __shared__ float w[MAXSEL];
    __shared__ int sidx[MAXSEL];

    for (int i = tid; i < k; i += blockDim.x) {
        w[i] = g_sel_score[r * MAXSEL + i];
        sidx[i] = g_sel_idx[r * MAXSEL + i];
    }
    __syncthreads();
    if (tid == 0) {
        float m = -3.402823e38f;
        for (int i = 0; i < k; i++) m = fmaxf(m, w[i]);
        float s = 0.f;
        for (int i = 0; i < k; i++) { w[i] = expf(w[i] - m); s += w[i]; }
        float inv = 1.0f / s;
        for (int i = 0; i < k; i++) w[i] *= inv;
    }
    __syncthreads();

    for (int d = tid; d < D; d += blockDim.x) {
        float a = 0.f;
        for (int i = 0; i < k; i++)
            a += w[i] * params[(size_t)sidx[i] * D + d];
        out[(size_t)r * D + d] = a;
    }
}

// ---------------- launch ----------------
extern "C" void kernel_launch(void* const* d_in, const int* in_sizes, int n_in,
                              void* d_out, int out_size)
{
    const float* hidden = (const float*)d_in[0];
    const float* params = (const float*)d_in[1];
    const float* keys   = (const float*)d_in[2];
    const float* W      = (const float*)d_in[3];
    const float* bias   = (const float*)d_in[4];
    const int*   kptr   = (const int*)d_in[5];
    const int*   mkptr  = (const int*)d_in[6];

    int D = (int)(sqrt((double)in_sizes[3]) + 0.5);   // W [D, D]
    int B = out_size / D;                              // out [B, D]
    int N = in_sizes[2] / D;                           // keys [N, D]
    int T = in_sizes[0] / (B * D);                     // hidden [B, T, D]
    float scale = 1.0f / sqrtf((float)D);

    float* out = (float*)d_out;

    cudaFuncSetAttribute(gemm_mma_kernel,
                         cudaFuncAttributeMaxDynamicSharedMemorySize, GEMM2_DYN);

    pool_mean_kernel<<<(B * D + 255) / 256, 256>>>(hidden, B, T, D);
    query_proj_kernel<<<B, 256>>>(W, bias, D);
    qsplit_kernel<<<(32 * D + 255) / 256, 256>>>(D);
    gemm_mma_kernel<<<(N + TN - 1) / TN, 256, GEMM2_DYN>>>(keys, N, D, scale);
    zero_scratch_kernel<<<(ROWS * NBIN + 255) / 256, 256>>>();
    hist_kernel<<<dim3(HCH, B), 256>>>(N);
    threshold_kernel<<<B, 256>>>(kptr, mkptr);
    compact_kernel<<<dim3(HCH, B), 256>>>(N);
    topk_final_kernel<<<B, SEL_T>>>(kptr, mkptr);
    aggregate_kernel<<<B, 256>>>(params, out, D, kptr, mkptr);
}

// round 12
// speedup vs baseline: 1.2517x; 1.1364x over previous
#include <cuda_runtime.h>
#include <cuda_bf16.h>
#include <math.h>
#include <stdint.h>

// ---------------- compile-time config ----------------
#define ROWS 32          // B (queries)
#define DMAX 1024
#define MAXSEL 1024
#define EQCAP 256
#define NBIN 4096
#define HCH 64
#define CAND 8192

// mma GEMM tiling
#define TN 128           // keys per CTA
#define KC 64            // dims per chunk
#define ASW2 72          // A chunk smem row stride (bf16): 36 words = 4 mod 32 -> LDSM conflict-free
#define KSW 72           // key smem row stride (bf16)
#define A_CH_BYTES (64 * ASW2 * 2)      // 9216
#define KMAT_BYTES (TN * KSW * 2)       // 18432
#define STAGE_B (A_CH_BYTES + 2 * KMAT_BYTES)   // 46080
#define GEMM2_DYN (2 * STAGE_B + 256)

typedef unsigned long long ull;

// ---------------- scratch (device globals; no runtime allocation) ----------------
__device__ float g_pooled[ROWS * DMAX];
__device__ float g_query[ROWS * DMAX];
__device__ __nv_bfloat16 g_ab[64 * DMAX];        // rows 0-31: qh, rows 32-63: ql
__device__ float g_scores[(size_t)ROWS * 500224];
__device__ float g_sel_score[ROWS * MAXSEL];
__device__ int   g_sel_idx[ROWS * MAXSEL];
__device__ unsigned g_hist[ROWS][NBIN];
__device__ unsigned g_thr[ROWS];
__device__ int      g_ccnt[ROWS];
__device__ float    g_cscore[ROWS * CAND];
__device__ int      g_cidx[ROWS * CAND];

// ---------------- helpers ----------------
__device__ __forceinline__ void cpa16(void* dst_smem, const void* src) {
    unsigned s = (unsigned)__cvta_generic_to_shared(dst_smem);
    asm volatile("cp.async.cg.shared.global [%0], [%1], 16;" :: "r"(s), "l"(src) : "memory");
}
__device__ __forceinline__ void cp_commit() { asm volatile("cp.async.commit_group;" ::: "memory"); }
__device__ __forceinline__ void cp_wait0()  { asm volatile("cp.async.wait_group 0;" ::: "memory"); }

__device__ __forceinline__ unsigned flipf(float f) {
    unsigned u = __float_as_uint(f);
    return (u & 0x80000000u) ? ~u : (u | 0x80000000u);
}
__device__ __forceinline__ float unflipf(unsigned u) {
    return __uint_as_float((u & 0x80000000u) ? (u ^ 0x80000000u) : ~u);
}
__device__ __forceinline__ int eff_k(const int* kptr, const int* mkptr) {
    int k = kptr[0];
    int mk = mkptr[0];
    if (mk < k) k = mk;
    if (k < 1) k = 1;
    if (k > MAXSEL) k = MAXSEL;
    return k;
}
// pack two fp32 -> bf16x2, f0 in low half (element order)
__device__ __forceinline__ uint32_t pk_bf(float f0, float f1) {
    uint32_t r;
    asm("cvt.rn.bf16x2.f32 %0, %1, %2;" : "=r"(r) : "f"(f1), "f"(f0));
    return r;
}
__device__ __forceinline__ float bf_lo(uint32_t w) { return __uint_as_float(w << 16); }
__device__ __forceinline__ float bf_hi(uint32_t w) { return __uint_as_float(w & 0xFFFF0000u); }

// bf16 m16n8k16 tensor-core MMA (sm_80+ PTX; valid on compute_103 base target)
__device__ __forceinline__ void mma16816(float* c, const uint32_t* a, const uint32_t* b) {
    asm volatile("mma.sync.aligned.m16n8k16.row.col.f32.bf16.bf16.f32 "
                 "{%0,%1,%2,%3}, {%4,%5,%6,%7}, {%8,%9}, {%0,%1,%2,%3};"
                 : "+f"(c[0]), "+f"(c[1]), "+f"(c[2]), "+f"(c[3])
                 : "r"(a[0]), "r"(a[1]), "r"(a[2]), "r"(a[3]), "r"(b[0]), "r"(b[1]));
}
// ldmatrix x4: four 8x8 b16 matrices; lanes 0-7/8-15/16-23/24-31 give row addrs of m0..m3
__device__ __forceinline__ void ldsm4(uint32_t* r, uint32_t addr) {
    asm volatile("ldmatrix.sync.aligned.m8n8.x4.shared.b16 {%0,%1,%2,%3}, [%4];"
                 : "=r"(r[0]), "=r"(r[1]), "=r"(r[2]), "=r"(r[3]) : "r"(addr));
}

// ---------------- K1a: pooled = mean(hidden, axis=T) ----------------
__global__ __launch_bounds__(256) void pool_mean_kernel(
    const float* __restrict__ hidden, int B, int T, int D)
{
    int gt = blockIdx.x * blockDim.x + threadIdx.x;
    if (gt >= B * D) return;
    int b = gt / D;
    int d = gt - b * D;
    const float* p = hidden + (size_t)b * T * D + d;
    float s = 0.f;
    #pragma unroll 8
    for (int t = 0; t < T; t++) s += p[(size_t)t * D];
    g_pooled[gt] = s * (1.0f / (float)T);
}

// ---------------- K1b: query = pooled @ W + bias ----------------
__global__ __launch_bounds__(256) void query_proj_kernel(
    const float* __restrict__ W, const float* __restrict__ bias, int D)
{
    int b = blockIdx.x;
    int tid = threadIdx.x;
    __shared__ float sp[DMAX];
    for (int i = tid; i < D; i += blockDim.x) sp[i] = g_pooled[b * D + i];
    __syncthreads();
    for (int d = tid; d < D; d += blockDim.x) {
        float a = bias[d];
        #pragma unroll 8
        for (int kx = 0; kx < D; kx++) a += sp[kx] * W[(size_t)kx * D + d];
        g_query[b * D + d] = a;
    }
}

// ---------------- K1c: split query -> bf16 hi/lo A [64][D] ----------------
__global__ __launch_bounds__(256) void qsplit_kernel(int D)
{
    int i = blockIdx.x * blockDim.x + threadIdx.x;
    if (i >= 32 * D) return;
    int row = i / D;
    int col = i - row * D;
    float f = g_query[row * D + col];
    __nv_bfloat16 h = __float2bfloat16(f);
    g_ab[row * D + col] = h;
    g_ab[(row + 32) * D + col] = __float2bfloat16(f - __bfloat162float(h));
}

// ---------------- K2: split-bf16 tensor-core score GEMM ----------------
// TN=128 keys x D per CTA. A ([qh;ql], 64xKC, cp.async) and keys (fp32->bf16
// hi/lo, STS) streamed per KC=64 chunk, double-buffered, ONE sync per chunk
// (next-stage cp.async issued post-sync => race-free). Fragment loads via
// ldmatrix.x4 (24 LDSM vs 96 LDS.32 per warp-chunk). 3 MMAs per fragment
// (qh*kh, ql*kh, qh*kl) -> exact to ~1e-9.
extern __shared__ char gdyn[];
__global__ __launch_bounds__(256, 2) void gemm_mma_kernel(
    const float* __restrict__ keys, int N, int D, float scale)
{
    const int tid = threadIdx.x;
    const int lane = tid & 31;
    const int wid = tid >> 5;
    const int g = lane >> 2;        // 0..7
    const int tig = lane & 3;       // 0..3
    const int mt = wid >> 2;        // 0..1  (score rows mt*16..+15)
    const int nq = wid & 3;         // 0..3  (ntiles nq*4..+3)
    const long long nbase = (long long)blockIdx.x * TN;

    // 128B-align dynamic smem
    uint32_t raw;
    asm("{ .reg .u64 t; cvta.to.shared.u64 t, %1; cvt.u32.u64 %0, t; }" : "=r"(raw) : "l"(gdyn));
    char* base = gdyn + (((raw + 127u) & ~127u) - raw);
    const uint32_t base_u = (raw + 127u) & ~127u;

    // per-stage layout: [A 64xASW2][KH TNxKSW][KL TNxKSW]
    __nv_bfloat16* Ast[2] = { (__nv_bfloat16*)base,
                              (__nv_bfloat16*)(base + STAGE_B) };
    __nv_bfloat16* KH[2]  = { (__nv_bfloat16*)(base + A_CH_BYTES),
                              (__nv_bfloat16*)(base + STAGE_B + A_CH_BYTES) };
    __nv_bfloat16* KL[2]  = { (__nv_bfloat16*)(base + A_CH_BYTES + KMAT_BYTES),
                              (__nv_bfloat16*)(base + STAGE_B + A_CH_BYTES + KMAT_BYTES) };

    const int nch = D / KC;

    // ldmatrix lane-role constants
    const int aquad = lane >> 3;
    const int arow  = (aquad & 1) * 8 + (lane & 7);
    const int akoff = (aquad >> 1) * 8;
    // byte offsets within A region
    const uint32_t a_off  = ((mt * 16 + arow) * ASW2 + akoff) * 2;
    const uint32_t AQL_D  = 32 * ASW2 * 2;
    // B: x4 packs (tile0,k0)(tile0,k0+8)(tile1,k0)(tile1,k0+8)
    const int bm      = lane >> 3;
    const int btile   = bm >> 1;            // 0/1 within pair
    const int bkoff   = (bm & 1) * 8;
    const int brow    = lane & 7;
    uint32_t b_off[2];
    #pragma unroll
    for (int tp = 0; tp < 2; tp++)
        b_off[tp] = (((nq * 4 + 2 * tp + btile) * 8 + brow) * KSW + bkoff) * 2;

    // A chunk loader: 64 rows x KC cols (128B per row = 8 x 16B), 512 slots
    auto load_A = [&](int st, int c) {
        #pragma unroll
        for (int it = 0; it < 2; it++) {
            int slot = tid + it * 256;        // 0..511
            int row = slot >> 3;              // 0..63
            int c16 = slot & 7;               // 16B chunk in row
            cpa16((char*)(Ast[st] + row * ASW2) + c16 * 16,
                  g_ab + (size_t)row * D + c * KC + c16 * 8);
        }
        cp_commit();
    };

    float acc[4][4];
    #pragma unroll
    for (int t = 0; t < 4; t++)
        #pragma unroll
        for (int j = 0; j < 4; j++) acc[t][j] = 0.f;

    // key row/half owned by this thread for staging
    const int krow = tid >> 1;          // 0..127
    const int khalf = tid & 1;          // 0..1 (32 floats each)
    long long grow = nbase + krow;
    if (grow >= N) grow = N - 1;
    const float* kbase = keys + grow * (long long)D + khalf * 32;

    // preload chunk 0
    load_A(0, 0);
    float4 R[8];
    #pragma unroll
    for (int q4 = 0; q4 < 8; q4++) R[q4] = *(const float4*)(kbase + q4 * 4);

    for (int c = 0; c < nch; c++) {
        const int st = c & 1;
        const uint32_t su = base_u + st * STAGE_B;

        // STS keys chunk c (convert fp32 -> bf16 hi/lo), 16B at a time
        {
            uint4* dh = (uint4*)((char*)(KH[st] + krow * KSW + khalf * 32));
            uint4* dl = (uint4*)((char*)(KL[st] + krow * KSW + khalf * 32));
            #pragma unroll
            for (int v = 0; v < 4; v++) {
                const float* f = (const float*)&R[2 * v];   // 8 floats
                uint32_t hw[4], lw[4];
                #pragma unroll
                for (int p = 0; p < 4; p++) {
                    float f0 = f[2 * p], f1 = f[2 * p + 1];
                    hw[p] = pk_bf(f0, f1);
                    lw[p] = pk_bf(f0 - bf_lo(hw[p]), f1 - bf_hi(hw[p]));
                }
                dh[v] = make_uint4(hw[0], hw[1], hw[2], hw[3]);
                dl[v] = make_uint4(lw[0], lw[1], lw[2], lw[3]);
            }
        }
        // prefetch next keys chunk into registers
        if (c + 1 < nch) {
            #pragma unroll
            for (int q4 = 0; q4 < 8; q4++)
                R[q4] = *(const float4*)(kbase + (c + 1) * KC + q4 * 4);
        }
        cp_wait0();        // own A(c) cp.asyncs done
        __syncthreads();   // ONE barrier per chunk: K(c)/A(c) visible; compute(c-1) done
        if (c + 1 < nch) load_A(st ^ 1, c + 1);   // post-sync: stage st^1 free

        // ---- compute chunk c (ldmatrix fragment loads) ----
        const uint32_t kh_u = su + A_CH_BYTES;
        const uint32_t kl_u = kh_u + KMAT_BYTES;
        #pragma unroll
        for (int ks = 0; ks < KC / 16; ks++) {
            const uint32_t kb = ks * 32;     // 16 bf16 = 32 bytes
            uint32_t aqh[4], aql[4];
            ldsm4(aqh, su + a_off + kb);
            ldsm4(aql, su + a_off + AQL_D + kb);
            #pragma unroll
            for (int tp = 0; tp < 2; tp++) {
                uint32_t bh[4], bl[4];
                ldsm4(bh, kh_u + b_off[tp] + kb);
                ldsm4(bl, kl_u + b_off[tp] + kb);
                mma16816(acc[2 * tp],     aqh, bh + 0);
                mma16816(acc[2 * tp],     aql, bh + 0);
                mma16816(acc[2 * tp],     aqh, bl + 0);
                mma16816(acc[2 * tp + 1], aqh, bh + 2);
                mma16816(acc[2 * tp + 1], aql, bh + 2);
                mma16816(acc[2 * tp + 1], aqh, bl + 2);
            }
        }
    }

    // ---- epilogue: write scores ----
    #pragma unroll
    for (int t = 0; t < 4; t++) {
        const int nt = nq * 4 + t;
        long long col = nbase + nt * 8 + 2 * tig;
        int row0 = mt * 16 + g;
        if (col + 1 < N) {
            *(float2*)&g_scores[(size_t)row0 * N + col] =
                make_float2(acc[t][0] * scale, acc[t][1] * scale);
            *(float2*)&g_scores[(size_t)(row0 + 8) * N + col] =
                make_float2(acc[t][2] * scale, acc[t][3] * scale);
        } else if (col < N) {
            g_scores[(size_t)row0 * N + col] = acc[t][0] * scale;
            g_scores[(size_t)(row0 + 8) * N + col] = acc[t][2] * scale;
        }
    }
}

// ---------------- K3a: zero scratch ----------------
__global__ __launch_bounds__(256) void zero_scratch_kernel()
{
    int i = blockIdx.x * blockDim.x + threadIdx.x;
    if (i < ROWS * NBIN) ((unsigned*)g_hist)[i] = 0;
    if (i < ROWS) g_ccnt[i] = 0;
}

// ---------------- K3b: grid-parallel per-row histogram ----------------
__global__ __launch_bounds__(256) void hist_kernel(int N)
{
    const int r = blockIdx.y;
    const int c = blockIdx.x;
    const int tid = threadIdx.x;
    __shared__ unsigned sh[NBIN];
    for (int i = tid; i < NBIN; i += 256) sh[i] = 0;
    __syncthreads();

    const int per = (N + HCH - 1) / HCH;
    const int s = c * per;
    const int e = (s + per < N) ? s + per : N;
    const float* srow = g_scores + (size_t)r * N;
    for (int i = s + tid; i < e; i += 256)
        atomicAdd(&sh[flipf(srow[i]) >> 20], 1u);
    __syncthreads();

    for (int i = tid; i < NBIN; i += 256)
        if (sh[i]) atomicAdd(&g_hist[r][i], sh[i]);
}

// ---------------- K3c: per-row threshold bin ----------------
__global__ __launch_bounds__(256) void threshold_kernel(
    const int* __restrict__ kptr, const int* __restrict__ mkptr)
{
    const int r = blockIdx.x;
    const int tid = threadIdx.x;
    __shared__ unsigned h[NBIN];
    __shared__ unsigned sfx[257];
    __shared__ int selg;

    const int k = eff_k(kptr, mkptr);
    for (int i = tid; i < NBIN; i += 256) h[i] = g_hist[r][i];
    __syncthreads();

    unsigned gsum = 0;
    #pragma unroll
    for (int b = 0; b < 16; b++) gsum += h[tid * 16 + b];
    sfx[tid] = gsum;
    if (tid == 0) sfx[256] = 0;
    __syncthreads();
    for (int off = 1; off < 256; off <<= 1) {
        unsigned t = (tid + off < 256) ? sfx[tid + off] : 0u;
        __syncthreads();
        sfx[tid] += t;
        __syncthreads();
    }
    unsigned above = (tid < 255) ? sfx[tid + 1] : 0u;
    if ((int)above < k && (int)sfx[tid] >= k) selg = tid;
    __syncthreads();

    if (tid == 0) {
        int g = selg;
        unsigned cum = (g < 255) ? sfx[g + 1] : 0u;
        int bsel = g * 16;
        for (int b = g * 16 + 15; b >= g * 16; b--) {
            cum += h[b];
            if ((int)cum >= k) { bsel = b; break; }
        }
        g_thr[r] = ((unsigned)bsel) << 20;
    }
}

// ---------------- K3d: compaction ----------------
__global__ __launch_bounds__(256) void compact_kernel(int N)
{
    const int r = blockIdx.y;
    const int c = blockIdx.x;
    const int tid = threadIdx.x;
    const unsigned thr = g_thr[r];

    const int per = (N + HCH - 1) / HCH;
    const int s = c * per;
    const int e = (s + per < N) ? s + per : N;
    const float* srow = g_scores + (size_t)r * N;
    for (int i = s + tid; i < e; i += 256) {
        float v = srow[i];
        if (flipf(v) >= thr) {
            int p = atomicAdd(&g_ccnt[r], 1);
            if (p < CAND) {
                g_cscore[r * CAND + p] = v;
                g_cidx[r * CAND + p] = i;
            }
        }
    }
}

// ---------------- K3e: exact top-k over candidates ----------------
#define SEL_T 256
__global__ __launch_bounds__(SEL_T) void topk_final_kernel(
    const int* __restrict__ kptr, const int* __restrict__ mkptr)
{
    const int r = blockIdx.x;
    const int tid = threadIdx.x;
    int M = g_ccnt[r];
    if (M > CAND) M = CAND;
    int k = eff_k(kptr, mkptr);
    if (k > M) k = M;

    const float* cs = g_cscore + r * CAND;
    const int*   ci = g_cidx + r * CAND;

    __shared__ unsigned bins[256];
    __shared__ unsigned sfx[257];
    __shared__ unsigned sh_prefix;
    __shared__ int sh_need;
    __shared__ int sh_selv;

    if (tid == 0) { sh_prefix = 0; sh_need = k; }
    __syncthreads();

    for (int pass = 0; pass < 4; pass++) {
        const int shift = 24 - 8 * pass;
        const unsigned hmask = pass ? (0xFFFFFFFFu << (shift + 8)) : 0u;
        bins[tid] = 0;
        __syncthreads();
        const unsigned pref = sh_prefix;
        for (int i = tid; i < M; i += SEL_T) {
            unsigned u = flipf(cs[i]);
            if ((u & hmask) == pref)
                atomicAdd(&bins[(u >> shift) & 255u], 1u);
        }
        __syncthreads();
        sfx[tid] = bins[tid];
        if (tid == 0) sfx[256] = 0;
        __syncthreads();
        for (int off = 1; off < 256; off <<= 1) {
            unsigned t = (tid + off < 256) ? sfx[tid + off] : 0u;
            __syncthreads();
            sfx[tid] += t;
            __syncthreads();
        }
        const int need = sh_need;
        const unsigned above = (tid < 255) ? sfx[tid + 1] : 0u;
        if ((int)above < need && (int)sfx[tid] >= need)
            sh_selv = tid;
        __syncthreads();
        if (tid == 0) {
            int v = sh_selv;
            sh_need = need - (int)((v < 255) ? sfx[v + 1] : 0u);
            sh_prefix = pref | ((unsigned)v << shift);
        }
        __syncthreads();
    }

    const unsigned uk = sh_prefix;
    const int need = sh_need;

    __shared__ int cg, ce;
    __shared__ int eq[EQCAP];
    if (tid == 0) { cg = 0; ce = 0; }
    __syncthreads();

    for (int i = tid; i < M; i += SEL_T) {
        unsigned u = flipf(cs[i]);
        if (u > uk) {
            int p = atomicAdd(&cg, 1);
            g_sel_score[r * MAXSEL + p] = cs[i];
            g_sel_idx[r * MAXSEL + p] = ci[i];
        } else if (u == uk) {
            int p = atomicAdd(&ce, 1);
            if (p < EQCAP) eq[p] = ci[i];
        }
    }
    __syncthreads();

    if (tid == 0) {
        const float tie_score = unflipf(uk);
        int base = cg;
        int ne = ce < EQCAP ? ce : EQCAP;
        for (int t = 0; t < need; t++) {
            int mv = 0x7FFFFFFF, mi = -1;
            for (int j = 0; j < ne; j++)
                if (eq[j] < mv) { mv = eq[j]; mi = j; }
            if (mi >= 0) eq[mi] = 0x7FFFFFFF;
            g_sel_idx[r * MAXSEL + base + t] = mv;
            g_sel_score[r * MAXSEL + base + t] = tie_score;
        }
        for (int a = 0; a < k - 1; a++) {
            int best = a;
            for (int bidx = a + 1; bidx < k; bidx++)
                if (g_sel_idx[r * MAXSEL + bidx] < g_sel_idx[r * MAXSEL + best]) best = bidx;
            if (best != a) {
                int ti = g_sel_idx[r * MAXSEL + a];
                g_sel_idx[r * MAXSEL + a] = g_sel_idx[r * MAXSEL + best];
                g_sel_idx[r * MAXSEL + best] = ti;
                float ts = g_sel_score[r * MAXSEL + a];
                g_sel_score[r * MAXSEL + a] = g_sel_score[r * MAXSEL + best];
                g_sel_score[r * MAXSEL + best] = ts;
            }
        }
    }
}

// ---------------- K4: softmax + weighted gather ----------------
__global__ __launch_bounds__(256) void aggregate_kernel(
    const float* __restrict__ params, float* __restrict__ out,
    int D, const int* __restrict__ kptr, const int* __restrict__ mkptr)
{
    const int r = blockIdx.x;
    const int tid = threadIdx.x;
    const int k = eff_k(kptr, mkptr);

    __shared__ float w[MAXSEL];
    __shared__ int sidx[MAXSEL];

    for (int i = tid; i < k; i += blockDim.x) {
        w[i] = g_sel_score[r * MAXSEL + i];
        sidx[i] = g_sel_idx[r * MAXSEL + i];
    }
    __syncthreads();
    if (tid == 0) {
        float m = -3.402823e38f;
        for (int i = 0; i < k; i++) m = fmaxf(m, w[i]);
        float s = 0.f;
        for (int i = 0; i < k; i++) { w[i] = expf(w[i] - m); s += w[i]; }
        float inv = 1.0f / s;
        for (int i = 0; i < k; i++) w[i] *= inv;
    }
    __syncthreads();

    for (int d = tid; d < D; d += blockDim.x) {
        float a = 0.f;
        for (int i = 0; i < k; i++)
            a += w[i] * params[(size_t)sidx[i] * D + d];
        out[(size_t)r * D + d] = a;
    }
}

// ---------------- launch ----------------
extern "C" void kernel_launch(void* const* d_in, const int* in_sizes, int n_in,
                              void* d_out, int out_size)
{
    const float* hidden = (const float*)d_in[0];
    const float* params = (const float*)d_in[1];
    const float* keys   = (const float*)d_in[2];
    const float* W      = (const float*)d_in[3];
    const float* bias   = (const float*)d_in[4];
    const int*   kptr   = (const int*)d_in[5];
    const int*   mkptr  = (const int*)d_in[6];

    int D = (int)(sqrt((double)in_sizes[3]) + 0.5);   // W [D, D]
    int B = out_size / D;                              // out [B, D]
    int N = in_sizes[2] / D;                           // keys [N, D]
    int T = in_sizes[0] / (B * D);                     // hidden [B, T, D]
    float scale = 1.0f / sqrtf((float)D);

    float* out = (float*)d_out;

    cudaFuncSetAttribute(gemm_mma_kernel,
                         cudaFuncAttributeMaxDynamicSharedMemorySize, GEMM2_DYN);

    zero_scratch_kernel<<<(ROWS * NBIN + 255) / 256, 256>>>();
    pool_mean_kernel<<<(B * D + 255) / 256, 256>>>(hidden, B, T, D);
    query_proj_kernel<<<B, 256>>>(W, bias, D);
    qsplit_kernel<<<(32 * D + 255) / 256, 256>>>(D);
    gemm_mma_kernel<<<(N + TN - 1) / TN, 256, GEMM2_DYN>>>(keys, N, D, scale);
    hist_kernel<<<dim3(HCH, B), 256>>>(N);
    threshold_kernel<<<B, 256>>>(kptr, mkptr);
    compact_kernel<<<dim3(HCH, B), 256>>>(N);
    topk_final_kernel<<<B, SEL_T>>>(kptr, mkptr);
    aggregate_kernel<<<B, 256>>>(params, out, D, kptr, mkptr);
}

// round 13
// speedup vs baseline: 1.4881x; 1.1889x over previous
#include <cuda_runtime.h>
#include <cuda_bf16.h>
#include <math.h>
#include <stdint.h>

// ---------------- compile-time config ----------------
#define ROWS 32          // B (queries)
#define DMAX 1024
#define MAXSEL 1024
#define EQCAP 256
#define NBIN 4096
#define HCH 64
#define CAND 8192

// mma GEMM tiling
#define TN 96            // keys per CTA (3 CTAs/SM)
#define KC 64            // dims per chunk
#define ASW2 72          // A chunk smem row stride (bf16): 36 words = 4 mod 32 -> LDSM conflict-free
#define KSW 72           // key smem row stride (bf16)
#define A_CH_BYTES (64 * ASW2 * 2)      // 9216
#define KMAT_BYTES (TN * KSW * 2)       // 13824
#define STAGE_B (A_CH_BYTES + 2 * KMAT_BYTES)   // 36864
#define GEMM2_DYN (2 * STAGE_B + 256)           // 73984 -> 3 CTAs/SM

typedef unsigned long long ull;

// ---------------- scratch (device globals; no runtime allocation) ----------------
__device__ float g_pooled[ROWS * DMAX];
__device__ __nv_bfloat16 g_ab[64 * DMAX];        // rows 0-31: qh, rows 32-63: ql
__device__ float g_scores[(size_t)ROWS * 500224];
__device__ float g_sel_score[ROWS * MAXSEL];
__device__ int   g_sel_idx[ROWS * MAXSEL];
__device__ unsigned g_hist[ROWS][NBIN];
__device__ unsigned g_thr[ROWS];
__device__ int      g_ccnt[ROWS];
__device__ float    g_cscore[ROWS * CAND];
__device__ int      g_cidx[ROWS * CAND];

// ---------------- helpers ----------------
__device__ __forceinline__ void cpa16(void* dst_smem, const void* src) {
    unsigned s = (unsigned)__cvta_generic_to_shared(dst_smem);
    asm volatile("cp.async.cg.shared.global [%0], [%1], 16;" :: "r"(s), "l"(src) : "memory");
}
__device__ __forceinline__ void cp_commit() { asm volatile("cp.async.commit_group;" ::: "memory"); }
__device__ __forceinline__ void cp_wait0()  { asm volatile("cp.async.wait_group 0;" ::: "memory"); }

__device__ __forceinline__ unsigned flipf(float f) {
    unsigned u = __float_as_uint(f);
    return (u & 0x80000000u) ? ~u : (u | 0x80000000u);
}
__device__ __forceinline__ float unflipf(unsigned u) {
    return __uint_as_float((u & 0x80000000u) ? (u ^ 0x80000000u) : ~u);
}
__device__ __forceinline__ int eff_k(const int* kptr, const int* mkptr) {
    int k = kptr[0];
    int mk = mkptr[0];
    if (mk < k) k = mk;
    if (k < 1) k = 1;
    if (k > MAXSEL) k = MAXSEL;
    return k;
}
// pack two fp32 -> bf16x2, f0 in low half (element order)
__device__ __forceinline__ uint32_t pk_bf(float f0, float f1) {
    uint32_t r;
    asm("cvt.rn.bf16x2.f32 %0, %1, %2;" : "=r"(r) : "f"(f1), "f"(f0));
    return r;
}
__device__ __forceinline__ float bf_lo(uint32_t w) { return __uint_as_float(w << 16); }
__device__ __forceinline__ float bf_hi(uint32_t w) { return __uint_as_float(w & 0xFFFF0000u); }

// bf16 m16n8k16 tensor-core MMA (sm_80+ PTX; valid on compute_103 base target)
__device__ __forceinline__ void mma16816(float* c, const uint32_t* a, const uint32_t* b) {
    asm volatile("mma.sync.aligned.m16n8k16.row.col.f32.bf16.bf16.f32 "
                 "{%0,%1,%2,%3}, {%4,%5,%6,%7}, {%8,%9}, {%0,%1,%2,%3};"
                 : "+f"(c[0]), "+f"(c[1]), "+f"(c[2]), "+f"(c[3])
                 : "r"(a[0]), "r"(a[1]), "r"(a[2]), "r"(a[3]), "r"(b[0]), "r"(b[1]));
}
// ldmatrix x4: four 8x8 b16 matrices
__device__ __forceinline__ void ldsm4(uint32_t* r, uint32_t addr) {
    asm volatile("ldmatrix.sync.aligned.m8n8.x4.shared.b16 {%0,%1,%2,%3}, [%4];"
                 : "=r"(r[0]), "=r"(r[1]), "=r"(r[2]), "=r"(r[3]) : "r"(addr));
}
// ldmatrix x2: two 8x8 b16 matrices (lanes 0-15 supply addresses)
__device__ __forceinline__ void ldsm2(uint32_t* r, uint32_t addr) {
    asm volatile("ldmatrix.sync.aligned.m8n8.x2.shared.b16 {%0,%1}, [%2];"
                 : "=r"(r[0]), "=r"(r[1]) : "r"(addr));
}

// ---------------- K1a: pooled = mean(hidden, axis=T) ----------------
__global__ __launch_bounds__(256) void pool_mean_kernel(
    const float* __restrict__ hidden, int B, int T, int D)
{
    int gt = blockIdx.x * blockDim.x + threadIdx.x;
    if (gt >= B * D) return;
    int b = gt / D;
    int d = gt - b * D;
    const float* p = hidden + (size_t)b * T * D + d;
    float s = 0.f;
    #pragma unroll 8
    for (int t = 0; t < T; t++) s += p[(size_t)t * D];
    g_pooled[gt] = s * (1.0f / (float)T);
}

// ---------------- K1b: query = pooled @ W + bias, split bf16 hi/lo -> g_ab ----------------
__global__ __launch_bounds__(256) void query_projsplit_kernel(
    const float* __restrict__ W, const float* __restrict__ bias, int D)
{
    int b = blockIdx.x;
    int tid = threadIdx.x;
    __shared__ float sp[DMAX];
    for (int i = tid; i < D; i += blockDim.x) sp[i] = g_pooled[b * D + i];
    __syncthreads();
    for (int d = tid; d < D; d += blockDim.x) {
        float a = bias[d];
        #pragma unroll 8
        for (int kx = 0; kx < D; kx++) a += sp[kx] * W[(size_t)kx * D + d];
        __nv_bfloat16 h = __float2bfloat16(a);
        g_ab[b * D + d] = h;
        g_ab[(b + 32) * D + d] = __float2bfloat16(a - __bfloat162float(h));
    }
}

// ---------------- K2: split-bf16 tensor-core score GEMM ----------------
// TN=96 keys x D per CTA, 3 CTAs/SM (24 warps: latency coverage; R12 LSU fix
// makes extra warps effective). A ([qh;ql], 64xKC, cp.async) + keys (LDG fp32
// -> bf16 hi/lo -> STS) per KC=64 chunk, double-buffered, one sync per chunk.
// Fragments via ldmatrix x4/x2. 3 MMAs per fragment (qh*kh, ql*kh, qh*kl).
extern __shared__ char gdyn[];
__global__ __launch_bounds__(256, 3) void gemm_mma_kernel(
    const float* __restrict__ keys, int N, int D, float scale)
{
    const int tid = threadIdx.x;
    const int lane = tid & 31;
    const int wid = tid >> 5;
    const int g = lane >> 2;        // 0..7
    const int tig = lane & 3;       // 0..3
    const int mt = wid >> 2;        // 0..1  (score rows mt*16..+15)
    const int nq = wid & 3;         // 0..3  (ntiles nq*3..+2)
    const long long nbase = (long long)blockIdx.x * TN;

    uint32_t raw;
    asm("{ .reg .u64 t; cvta.to.shared.u64 t, %1; cvt.u32.u64 %0, t; }" : "=r"(raw) : "l"(gdyn));
    char* base = gdyn + (((raw + 127u) & ~127u) - raw);
    const uint32_t base_u = (raw + 127u) & ~127u;

    __nv_bfloat16* Ast[2] = { (__nv_bfloat16*)base,
                              (__nv_bfloat16*)(base + STAGE_B) };
    __nv_bfloat16* KH[2]  = { (__nv_bfloat16*)(base + A_CH_BYTES),
                              (__nv_bfloat16*)(base + STAGE_B + A_CH_BYTES) };
    __nv_bfloat16* KL[2]  = { (__nv_bfloat16*)(base + A_CH_BYTES + KMAT_BYTES),
                              (__nv_bfloat16*)(base + STAGE_B + A_CH_BYTES + KMAT_BYTES) };

    const int nch = D / KC;

    // ldmatrix lane-role constants
    const int aquad = lane >> 3;
    const int arow  = (aquad & 1) * 8 + (lane & 7);
    const int akoff = (aquad >> 1) * 8;
    const uint32_t a_off  = ((mt * 16 + arow) * ASW2 + akoff) * 2;
    const uint32_t AQL_D  = 32 * ASW2 * 2;
    // B pair (tiles nq*3+0, nq*3+1) via x4: m order (t0,k0)(t0,k8)(t1,k0)(t1,k8)
    const int bm    = lane >> 3;
    const int btile = bm >> 1;
    const int bkoff = (bm & 1) * 8;
    const int brow  = lane & 7;
    const uint32_t b_off_pair =
        (((nq * 3 + btile) * 8 + brow) * KSW + bkoff) * 2;
    // B single (tile nq*3+2) via x2: lanes 0-15 -> (t2,k0)(t2,k8)
    const uint32_t b_off_sing =
        (((nq * 3 + 2) * 8 + (lane & 7)) * KSW + ((lane >> 3) & 1) * 8) * 2;

    // A chunk loader
    auto load_A = [&](int st, int c) {
        #pragma unroll
        for (int it = 0; it < 2; it++) {
            int slot = tid + it * 256;        // 0..511
            int row = slot >> 3;              // 0..63
            int c16 = slot & 7;
            cpa16((char*)(Ast[st] + row * ASW2) + c16 * 16,
                  g_ab + (size_t)row * D + c * KC + c16 * 8);
        }
        cp_commit();
    };

    float acc[3][4];
    #pragma unroll
    for (int t = 0; t < 3; t++)
        #pragma unroll
        for (int j = 0; j < 4; j++) acc[t][j] = 0.f;

    // key staging: slot = row*16 + q4; 96*16 = 1536 slots, 6 per thread
    load_A(0, 0);

    for (int c = 0; c < nch; c++) {
        const int st = c & 1;
        const uint32_t su = base_u + st * STAGE_B;

        // LDG fp32 keys chunk c -> convert -> STS (no reg prefetch; 24 warps hide LDG)
        #pragma unroll
        for (int it = 0; it < 6; it++) {
            int slot = tid + it * 256;        // 0..1535
            int row = slot >> 4;              // 0..95
            int q4  = slot & 15;              // float4 index in 64-col chunk
            long long grow = nbase + row;
            if (grow >= N) grow = N - 1;
            float4 v = *(const float4*)(keys + grow * (long long)D + c * KC + q4 * 4);
            uint32_t h0 = pk_bf(v.x, v.y);
            uint32_t h1 = pk_bf(v.z, v.w);
            uint32_t l0 = pk_bf(v.x - bf_lo(h0), v.y - bf_hi(h0));
            uint32_t l1 = pk_bf(v.z - bf_lo(h1), v.w - bf_hi(h1));
            char* dh = (char*)(KH[st] + row * KSW) + q4 * 8;
            char* dl = (char*)(KL[st] + row * KSW) + q4 * 8;
            *(uint2*)dh = make_uint2(h0, h1);
            *(uint2*)dl = make_uint2(l0, l1);
        }
        cp_wait0();        // own A(c) cp.asyncs done
        __syncthreads();   // one barrier: K(c)/A(c) visible; compute(c-1) done
        if (c + 1 < nch) load_A(st ^ 1, c + 1);   // post-sync: stage st^1 free

        // ---- compute chunk c ----
        const uint32_t kh_u = su + A_CH_BYTES;
        const uint32_t kl_u = kh_u + KMAT_BYTES;
        #pragma unroll
        for (int ks = 0; ks < KC / 16; ks++) {
            const uint32_t kb = ks * 32;
            uint32_t aqh[4], aql[4];
            ldsm4(aqh, su + a_off + kb);
            ldsm4(aql, su + a_off + AQL_D + kb);
            {
                uint32_t bh[4], bl[4];
                ldsm4(bh, kh_u + b_off_pair + kb);
                ldsm4(bl, kl_u + b_off_pair + kb);
                mma16816(acc[0], aqh, bh + 0);
                mma16816(acc[0], aql, bh + 0);
                mma16816(acc[0], aqh, bl + 0);
                mma16816(acc[1], aqh, bh + 2);
                mma16816(acc[1], aql, bh + 2);
                mma16816(acc[1], aqh, bl + 2);
            }
            {
                uint32_t bh[2], bl[2];
                ldsm2(bh, kh_u + b_off_sing + kb);
                ldsm2(bl, kl_u + b_off_sing + kb);
                mma16816(acc[2], aqh, bh);
                mma16816(acc[2], aql, bh);
                mma16816(acc[2], aqh, bl);
            }
        }
    }

    // ---- epilogue: write scores ----
    #pragma unroll
    for (int t = 0; t < 3; t++) {
        const int nt = nq * 3 + t;
        long long col = nbase + nt * 8 + 2 * tig;
        int row0 = mt * 16 + g;
        if (col + 1 < N) {
            *(float2*)&g_scores[(size_t)row0 * N + col] =
                make_float2(acc[t][0] * scale, acc[t][1] * scale);
            *(float2*)&g_scores[(size_t)(row0 + 8) * N + col] =
                make_float2(acc[t][2] * scale, acc[t][3] * scale);
        } else if (col < N) {
            g_scores[(size_t)row0 * N + col] = acc[t][0] * scale;
            g_scores[(size_t)(row0 + 8) * N + col] = acc[t][2] * scale;
        }
    }
}

// ---------------- K3a: zero scratch ----------------
__global__ __launch_bounds__(256) void zero_scratch_kernel()
{
    int i = blockIdx.x * blockDim.x + threadIdx.x;
    if (i < ROWS * NBIN) ((unsigned*)g_hist)[i] = 0;
    if (i < ROWS) g_ccnt[i] = 0;
}

// ---------------- K3b: grid-parallel per-row histogram ----------------
__global__ __launch_bounds__(256) void hist_kernel(int N)
{
    const int r = blockIdx.y;
    const int c = blockIdx.x;
    const int tid = threadIdx.x;
    __shared__ unsigned sh[NBIN];
    for (int i = tid; i < NBIN; i += 256) sh[i] = 0;
    __syncthreads();

    const int per = (N + HCH - 1) / HCH;
    const int s = c * per;
    const int e = (s + per < N) ? s + per : N;
    const float* srow = g_scores + (size_t)r * N;
    for (int i = s + tid; i < e; i += 256)
        atomicAdd(&sh[flipf(srow[i]) >> 20], 1u);
    __syncthreads();

    for (int i = tid; i < NBIN; i += 256)
        if (sh[i]) atomicAdd(&g_hist[r][i], sh[i]);
}

// ---------------- K3c: per-row threshold bin ----------------
__global__ __launch_bounds__(256) void threshold_kernel(
    const int* __restrict__ kptr, const int* __restrict__ mkptr)
{
    const int r = blockIdx.x;
    const int tid = threadIdx.x;
    __shared__ unsigned h[NBIN];
    __shared__ unsigned sfx[257];
    __shared__ int selg;

    const int k = eff_k(kptr, mkptr);
    for (int i = tid; i < NBIN; i += 256) h[i] = g_hist[r][i];
    __syncthreads();

    unsigned gsum = 0;
    #pragma unroll
    for (int b = 0; b < 16; b++) gsum += h[tid * 16 + b];
    sfx[tid] = gsum;
    if (tid == 0) sfx[256] = 0;
    __syncthreads();
    for (int off = 1; off < 256; off <<= 1) {
        unsigned t = (tid + off < 256) ? sfx[tid + off] : 0u;
        __syncthreads();
        sfx[tid] += t;
        __syncthreads();
    }
    unsigned above = (tid < 255) ? sfx[tid + 1] : 0u;
    if ((int)above < k && (int)sfx[tid] >= k) selg = tid;
    __syncthreads();

    if (tid == 0) {
        int g = selg;
        unsigned cum = (g < 255) ? sfx[g + 1] : 0u;
        int bsel = g * 16;
        for (int b = g * 16 + 15; b >= g * 16; b--) {
            cum += h[b];
            if ((int)cum >= k) { bsel = b; break; }
        }
        g_thr[r] = ((unsigned)bsel) << 20;
    }
}

// ---------------- K3d: compaction ----------------
__global__ __launch_bounds__(256) void compact_kernel(int N)
{
    const int r = blockIdx.y;
    const int c = blockIdx.x;
    const int tid = threadIdx.x;
    const unsigned thr = g_thr[r];

    const int per = (N + HCH - 1) / HCH;
    const int s = c * per;
    const int e = (s + per < N) ? s + per : N;
    const float* srow = g_scores + (size_t)r * N;
    for (int i = s + tid; i < e; i += 256) {
        float v = srow[i];
        if (flipf(v) >= thr) {
            int p = atomicAdd(&g_ccnt[r], 1);
            if (p < CAND) {
                g_cscore[r * CAND + p] = v;
                g_cidx[r * CAND + p] = i;
            }
        }
    }
}

// ---------------- K3e: exact top-k over candidates ----------------
#define SEL_T 256
__global__ __launch_bounds__(SEL_T) void topk_final_kernel(
    const int* __restrict__ kptr, const int* __restrict__ mkptr)
{
    const int r = blockIdx.x;
    const int tid = threadIdx.x;
    int M = g_ccnt[r];
    if (M > CAND) M = CAND;
    int k = eff_k(kptr, mkptr);
    if (k > M) k = M;

    const float* cs = g_cscore + r * CAND;
    const int*   ci = g_cidx + r * CAND;

    __shared__ unsigned bins[256];
    __shared__ unsigned sfx[257];
    __shared__ unsigned sh_prefix;
    __shared__ int sh_need;
    __shared__ int sh_selv;

    if (tid == 0) { sh_prefix = 0; sh_need = k; }
    __syncthreads();

    for (int pass = 0; pass < 4; pass++) {
        const int shift = 24 - 8 * pass;
        const unsigned hmask = pass ? (0xFFFFFFFFu << (shift + 8)) : 0u;
        bins[tid] = 0;
        __syncthreads();
        const unsigned pref = sh_prefix;
        for (int i = tid; i < M; i += SEL_T) {
            unsigned u = flipf(cs[i]);
            if ((u & hmask) == pref)
                atomicAdd(&bins[(u >> shift) & 255u], 1u);
        }
        __syncthreads();
        sfx[tid] = bins[tid];
        if (tid == 0) sfx[256] = 0;
        __syncthreads();
        for (int off = 1; off < 256; off <<= 1) {
            unsigned t = (tid + off < 256) ? sfx[tid + off] : 0u;
            __syncthreads();
            sfx[tid] += t;
            __syncthreads();
        }
        const int need = sh_need;
        const unsigned above = (tid < 255) ? sfx[tid + 1] : 0u;
        if ((int)above < need && (int)sfx[tid] >= need)
            sh_selv = tid;
        __syncthreads();
        if (tid == 0) {
            int v = sh_selv;
            sh_need = need - (int)((v < 255) ? sfx[v + 1] : 0u);
            sh_prefix = pref | ((unsigned)v << shift);
        }
        __syncthreads();
    }

    const unsigned uk = sh_prefix;
    const int need = sh_need;

    __shared__ int cg, ce;
    __shared__ int eq[EQCAP];
    if (tid == 0) { cg = 0; ce = 0; }
    __syncthreads();

    for (int i = tid; i < M; i += SEL_T) {
        unsigned u = flipf(cs[i]);
        if (u > uk) {
            int p = atomicAdd(&cg, 1);
            g_sel_score[r * MAXSEL + p] = cs[i];
            g_sel_idx[r * MAXSEL + p] = ci[i];
        } else if (u == uk) {
            int p = atomicAdd(&ce, 1);
            if (p < EQCAP) eq[p] = ci[i];
        }
    }
    __syncthreads();

    if (tid == 0) {
        const float tie_score = unflipf(uk);
        int base = cg;
        int ne = ce < EQCAP ? ce : EQCAP;
        for (int t = 0; t < need; t++) {
            int mv = 0x7FFFFFFF, mi = -1;
            for (int j = 0; j < ne; j++)
                if (eq[j] < mv) { mv = eq[j]; mi = j; }
            if (mi >= 0) eq[mi] = 0x7FFFFFFF;
            g_sel_idx[r * MAXSEL + base + t] = mv;
            g_sel_score[r * MAXSEL + base + t] = tie_score;
        }
        for (int a = 0; a < k - 1; a++) {
            int best = a;
            for (int bidx = a + 1; bidx < k; bidx++)
                if (g_sel_idx[r * MAXSEL + bidx] < g_sel_idx[r * MAXSEL + best]) best = bidx;
            if (best != a) {
                int ti = g_sel_idx[r * MAXSEL + a];
                g_sel_idx[r * MAXSEL + a] = g_sel_idx[r * MAXSEL + best];
                g_sel_idx[r * MAXSEL + best] = ti;
                float ts = g_sel_score[r * MAXSEL + a];
                g_sel_score[r * MAXSEL + a] = g_sel_score[r * MAXSEL + best];
                g_sel_score[r * MAXSEL + best] = ts;
            }
        }
    }
}

// ---------------- K4: softmax + weighted gather ----------------
__global__ __launch_bounds__(256) void aggregate_kernel(
    const float* __restrict__ params, float* __restrict__ out,
    int D, const int* __restrict__ kptr, const int* __restrict__ mkptr)
{
    const int r = blockIdx.x;
    const int tid = threadIdx.x;
    const int k = eff_k(kptr, mkptr);

    __shared__ float w[MAXSEL];
    __shared__ int sidx[MAXSEL];

    for (int i = tid; i < k; i += blockDim.x) {
        w[i] = g_sel_score[r * MAXSEL + i];
        sidx[i] = g_sel_idx[r * MAXSEL + i];
    }
    __syncthreads();
    if (tid == 0) {
        float m = -3.402823e38f;
        for (int i = 0; i < k; i++) m = fmaxf(m, w[i]);
        float s = 0.f;
        for (int i = 0; i < k; i++) { w[i] = expf(w[i] - m); s += w[i]; }
        float inv = 1.0f / s;
        for (int i = 0; i < k; i++) w[i] *= inv;
    }
    __syncthreads();

    for (int d = tid; d < D; d += blockDim.x) {
        float a = 0.f;
        for (int i = 0; i < k; i++)
            a += w[i] * params[(size_t)sidx[i] * D + d];
        out[(size_t)r * D + d] = a;
    }
}

// ---------------- launch ----------------
extern "C" void kernel_launch(void* const* d_in, const int* in_sizes, int n_in,
                              void* d_out, int out_size)
{
    const float* hidden = (const float*)d_in[0];
    const float* params = (const float*)d_in[1];
    const float* keys   = (const float*)d_in[2];
    const float* W      = (const float*)d_in[3];
    const float* bias   = (const float*)d_in[4];
    const int*   kptr   = (const int*)d_in[5];
    const int*   mkptr  = (const int*)d_in[6];

    int D = (int)(sqrt((double)in_sizes[3]) + 0.5);   // W [D, D]
    int B = out_size / D;                              // out [B, D]
    int N = in_sizes[2] / D;                           // keys [N, D]
    int T = in_sizes[0] / (B * D);                     // hidden [B, T, D]
    float scale = 1.0f / sqrtf((float)D);

    float* out = (float*)d_out;

    cudaFuncSetAttribute(gemm_mma_kernel,
                         cudaFuncAttributeMaxDynamicSharedMemorySize, GEMM2_DYN);

    zero_scratch_kernel<<<(ROWS * NBIN + 255) / 256, 256>>>();
    pool_mean_kernel<<<(B * D + 255) / 256, 256>>>(hidden, B, T, D);
    query_projsplit_kernel<<<B, 256>>>(W, bias, D);
    gemm_mma_kernel<<<(N + TN - 1) / TN, 256, GEMM2_DYN>>>(keys, N, D, scale);
    hist_kernel<<<dim3(HCH, B), 256>>>(N);
    threshold_kernel<<<B, 256>>>(kptr, mkptr);
    compact_kernel<<<dim3(HCH, B), 256>>>(N);
    topk_final_kernel<<<B, SEL_T>>>(kptr, mkptr);
    aggregate_kernel<<<B, 256>>>(params, out, D, kptr, mkptr);
}